// round 12
// baseline (speedup 1.0000x reference)
#include <cuda_runtime.h>
#include <cuda_fp16.h>
#include <cstdint>

// EmbeddingBag(mode='sum') + bias — fused persistent kernel, v2.
//
// Validated model: runtime == total LTS bytes / chip LTS cap (~14 TB/s).
// Bytes are at floor (fp16 gather). v1 fusion lost to 11% warp load
// imbalance (2.69 bags/warp -> makespan 3) and 48 regs. v2:
//   - grid = 1024 CTAs (co-resident at 32 regs) -> 8192 warps x exactly
//     2 bags: zero imbalance quantum.
//   - __launch_bounds__(256, 8) pins 32 regs; simple tree-of-4 body
//     (index prefetch was proven neutral).
//   - phase 1: grid-stride fp32->fp16 convert; grid-wide generation
//     barrier (monotone across graph replays); phase 2: warp-per-bag
//     gather (LDG.128 rows, fp16 tree-of-4, fp32 accumulate + bias).

#define HIDDEN   256
#define MAX_ROWS 6144
#define ROW_U4   32   // 256 halves = 512B = 32 uint4 per row

__device__ __half    g_table_h[MAX_ROWS * HIDDEN];  // 3 MB scratch
__device__ unsigned  g_arrive = 0;
__device__ unsigned  g_gen    = 0;

__device__ __forceinline__ unsigned h2_to_u(__half2 h) {
    unsigned u; memcpy(&u, &h, 4); return u;
}
__device__ __forceinline__ __half2 u_to_h2(unsigned u) {
    __half2 h; memcpy(&h, &u, 4); return h;
}

__device__ __forceinline__ void tree4_acc(float acc[8],
                                          const uint4& v0, const uint4& v1,
                                          const uint4& v2, const uint4& v3)
{
    __half2 s0 = __hadd2(__hadd2(u_to_h2(v0.x), u_to_h2(v1.x)),
                         __hadd2(u_to_h2(v2.x), u_to_h2(v3.x)));
    __half2 s1 = __hadd2(__hadd2(u_to_h2(v0.y), u_to_h2(v1.y)),
                         __hadd2(u_to_h2(v2.y), u_to_h2(v3.y)));
    __half2 s2 = __hadd2(__hadd2(u_to_h2(v0.z), u_to_h2(v1.z)),
                         __hadd2(u_to_h2(v2.z), u_to_h2(v3.z)));
    __half2 s3 = __hadd2(__hadd2(u_to_h2(v0.w), u_to_h2(v1.w)),
                         __hadd2(u_to_h2(v2.w), u_to_h2(v3.w)));
    float2 f0 = __half22float2(s0);
    float2 f1 = __half22float2(s1);
    float2 f2 = __half22float2(s2);
    float2 f3 = __half22float2(s3);
    acc[0] += f0.x; acc[1] += f0.y;
    acc[2] += f1.x; acc[3] += f1.y;
    acc[4] += f2.x; acc[5] += f2.y;
    acc[6] += f3.x; acc[7] += f3.y;
}

__device__ __forceinline__ void one_acc(float acc[8], const uint4& v)
{
    float2 f0 = __half22float2(u_to_h2(v.x));
    float2 f1 = __half22float2(u_to_h2(v.y));
    float2 f2 = __half22float2(u_to_h2(v.z));
    float2 f3 = __half22float2(u_to_h2(v.w));
    acc[0] += f0.x; acc[1] += f0.y;
    acc[2] += f1.x; acc[3] += f1.y;
    acc[4] += f2.x; acc[5] += f2.y;
    acc[6] += f3.x; acc[7] += f3.y;
}

__global__ __launch_bounds__(256, 8)
void embag_fused2_kernel(const int* __restrict__ idx,
                         const int* __restrict__ offs,
                         const float4* __restrict__ table4,
                         const float* __restrict__ bias,
                         float* __restrict__ out,
                         int batch, int n_total, int n8)
{
    // ------------- phase 1: fp32 -> fp16 convert (grid-stride) -------------
    const int gtid     = blockIdx.x * blockDim.x + threadIdx.x;
    const int gthreads = gridDim.x * blockDim.x;
    for (int t = gtid; t < n8; t += gthreads) {
        float4 a = __ldg(table4 + 2 * t);
        float4 b = __ldg(table4 + 2 * t + 1);
        uint4 v;
        v.x = h2_to_u(__floats2half2_rn(a.x, a.y));
        v.y = h2_to_u(__floats2half2_rn(a.z, a.w));
        v.z = h2_to_u(__floats2half2_rn(b.x, b.y));
        v.w = h2_to_u(__floats2half2_rn(b.z, b.w));
        reinterpret_cast<uint4*>(g_table_h)[t] = v;
    }
    __threadfence();
    __syncthreads();

    // ------------- grid-wide generation barrier ----------------------------
    if (threadIdx.x == 0) {
        const unsigned gen = atomicAdd(&g_gen, 0u);
        const unsigned ticket = atomicAdd(&g_arrive, 1u);
        if (ticket == gridDim.x - 1) {
            g_arrive = 0;
            __threadfence();
            atomicAdd(&g_gen, 1u);   // release
        } else {
            while (atomicAdd(&g_gen, 0u) == gen) { __nanosleep(64); }
        }
    }
    __syncthreads();
    __threadfence();

    // ------------- phase 2: warp-per-bag gather-sum ------------------------
    const int lane    = threadIdx.x & 31;
    const int nwarps  = gthreads >> 5;
    const int mywarp  = gtid >> 5;
    const int bpw     = (batch + nwarps - 1) / nwarps;   // ==2 at grid 1024
    const int bag_lo  = mywarp * bpw;
    const int bag_hi  = min(bag_lo + bpw, batch);

    const uint4* base = reinterpret_cast<const uint4*>(g_table_h) + lane;

    for (int bag = bag_lo; bag < bag_hi; ++bag) {
        const int start = __ldg(offs + bag);
        const int end   = (bag + 1 < batch) ? __ldg(offs + bag + 1) : n_total;

        float acc[8];
        {
            float4 b0 = __ldg(reinterpret_cast<const float4*>(bias) + 2 * lane);
            float4 b1 = __ldg(reinterpret_cast<const float4*>(bias) + 2 * lane + 1);
            acc[0] = b0.x; acc[1] = b0.y; acc[2] = b0.z; acc[3] = b0.w;
            acc[4] = b1.x; acc[5] = b1.y; acc[6] = b1.z; acc[7] = b1.w;
        }

        int j = start;
        for (; j + 4 <= end; j += 4) {
            const int i0 = __ldg(idx + j + 0);
            const int i1 = __ldg(idx + j + 1);
            const int i2 = __ldg(idx + j + 2);
            const int i3 = __ldg(idx + j + 3);
            const uint4 v0 = base[(size_t)i0 * ROW_U4];
            const uint4 v1 = base[(size_t)i1 * ROW_U4];
            const uint4 v2 = base[(size_t)i2 * ROW_U4];
            const uint4 v3 = base[(size_t)i3 * ROW_U4];
            tree4_acc(acc, v0, v1, v2, v3);
        }
        for (; j < end; ++j) {
            const int i = __ldg(idx + j);
            one_acc(acc, base[(size_t)i * ROW_U4]);
        }

        float4* o = reinterpret_cast<float4*>(out + (size_t)bag * HIDDEN) + 2 * lane;
        o[0] = make_float4(acc[0], acc[1], acc[2], acc[3]);
        o[1] = make_float4(acc[4], acc[5], acc[6], acc[7]);
    }
}

extern "C" void kernel_launch(void* const* d_in, const int* in_sizes, int n_in,
                              void* d_out, int out_size)
{
    const int*    feature_indices = (const int*)d_in[0];
    const int*    offsets         = (const int*)d_in[1];
    const float4* table4          = (const float4*)d_in[2];
    const float*  bias            = (const float*)d_in[3];
    float*        out             = (float*)d_out;

    const int n_total     = in_sizes[0];
    const int batch       = in_sizes[1];
    const int table_elems = in_sizes[2];
    const int n8          = table_elems / 8;

    // Grid: as close to 1024 as co-residency allows (spin barrier requires
    // all CTAs resident in one wave). Host-only queries; deterministic.
    static int s_grid = 0;
    if (s_grid == 0) {
        int dev = 0, sms = 0, maxb = 0;
        cudaGetDevice(&dev);
        cudaDeviceGetAttribute(&sms, cudaDevAttrMultiProcessorCount, dev);
        cudaOccupancyMaxActiveBlocksPerMultiprocessor(&maxb, embag_fused2_kernel,
                                                      256, 0);
        if (sms <= 0)  sms = 148;
        if (maxb <= 0) maxb = 1;
        int cap = sms * maxb;
        s_grid = cap < 1024 ? cap : 1024;
    }

    embag_fused2_kernel<<<s_grid, 256>>>(feature_indices, offsets, table4, bias,
                                         out, batch, n_total, n8);
}

// round 13
// speedup vs baseline: 1.0708x; 1.0708x over previous
#include <cuda_runtime.h>
#include <cuda_fp16.h>
#include <cstdint>

// EmbeddingBag(mode='sum') + bias — fused persistent kernel, v3.
//
// Validated model: runtime == total LTS bytes / chip LTS cap (~14 TB/s);
// bytes are at floor. v2's regression was barrier ATOMIC-POLL contention
// (RMW polls serialize ~27cyc/op at the LTS atomic unit; 1023 pollers
// saturate it). v3 keeps v2's exact 2-bags-per-warp balance and replaces
// the poll with a contention-free spin:
//   - waiters spin on a PLAIN ld.global.cg of g_gen (L2 broadcast, no RMW)
//   - release is one red.global.add after a __threadfence
//   - arrivals remain one-shot atomicAdd tickets
// Generation counter is monotone across graph replays (no reset hazard).

#define HIDDEN   256
#define MAX_ROWS 6144
#define ROW_U4   32   // 256 halves = 512B = 32 uint4 per row

__device__ __half    g_table_h[MAX_ROWS * HIDDEN];  // 3 MB scratch
__device__ unsigned  g_arrive = 0;
__device__ unsigned  g_gen    = 0;

__device__ __forceinline__ unsigned h2_to_u(__half2 h) {
    unsigned u; memcpy(&u, &h, 4); return u;
}
__device__ __forceinline__ __half2 u_to_h2(unsigned u) {
    __half2 h; memcpy(&h, &u, 4); return h;
}

__device__ __forceinline__ unsigned ldcg_u32(const unsigned* p) {
    unsigned v;
    asm volatile("ld.global.cg.u32 %0, [%1];" : "=r"(v) : "l"(p));
    return v;
}

__device__ __forceinline__ void tree4_acc(float acc[8],
                                          const uint4& v0, const uint4& v1,
                                          const uint4& v2, const uint4& v3)
{
    __half2 s0 = __hadd2(__hadd2(u_to_h2(v0.x), u_to_h2(v1.x)),
                         __hadd2(u_to_h2(v2.x), u_to_h2(v3.x)));
    __half2 s1 = __hadd2(__hadd2(u_to_h2(v0.y), u_to_h2(v1.y)),
                         __hadd2(u_to_h2(v2.y), u_to_h2(v3.y)));
    __half2 s2 = __hadd2(__hadd2(u_to_h2(v0.z), u_to_h2(v1.z)),
                         __hadd2(u_to_h2(v2.z), u_to_h2(v3.z)));
    __half2 s3 = __hadd2(__hadd2(u_to_h2(v0.w), u_to_h2(v1.w)),
                         __hadd2(u_to_h2(v2.w), u_to_h2(v3.w)));
    float2 f0 = __half22float2(s0);
    float2 f1 = __half22float2(s1);
    float2 f2 = __half22float2(s2);
    float2 f3 = __half22float2(s3);
    acc[0] += f0.x; acc[1] += f0.y;
    acc[2] += f1.x; acc[3] += f1.y;
    acc[4] += f2.x; acc[5] += f2.y;
    acc[6] += f3.x; acc[7] += f3.y;
}

__device__ __forceinline__ void one_acc(float acc[8], const uint4& v)
{
    float2 f0 = __half22float2(u_to_h2(v.x));
    float2 f1 = __half22float2(u_to_h2(v.y));
    float2 f2 = __half22float2(u_to_h2(v.z));
    float2 f3 = __half22float2(u_to_h2(v.w));
    acc[0] += f0.x; acc[1] += f0.y;
    acc[2] += f1.x; acc[3] += f1.y;
    acc[4] += f2.x; acc[5] += f2.y;
    acc[6] += f3.x; acc[7] += f3.y;
}

__global__ __launch_bounds__(256, 8)
void embag_fused3_kernel(const int* __restrict__ idx,
                         const int* __restrict__ offs,
                         const float4* __restrict__ table4,
                         const float* __restrict__ bias,
                         float* __restrict__ out,
                         int batch, int n_total, int n8)
{
    // ------------- phase 1: fp32 -> fp16 convert (grid-stride) -------------
    const int gtid     = blockIdx.x * blockDim.x + threadIdx.x;
    const int gthreads = gridDim.x * blockDim.x;
    for (int t = gtid; t < n8; t += gthreads) {
        float4 a = __ldg(table4 + 2 * t);
        float4 b = __ldg(table4 + 2 * t + 1);
        uint4 v;
        v.x = h2_to_u(__floats2half2_rn(a.x, a.y));
        v.y = h2_to_u(__floats2half2_rn(a.z, a.w));
        v.z = h2_to_u(__floats2half2_rn(b.x, b.y));
        v.w = h2_to_u(__floats2half2_rn(b.z, b.w));
        reinterpret_cast<uint4*>(g_table_h)[t] = v;
    }
    __threadfence();       // table writes visible before arrival
    __syncthreads();

    // ------------- grid-wide barrier: atomic arrive, LOAD-spin wait --------
    if (threadIdx.x == 0) {
        const unsigned gen    = ldcg_u32(&g_gen);          // snapshot first
        const unsigned ticket = atomicAdd(&g_arrive, 1u);
        if (ticket == gridDim.x - 1) {
            g_arrive = 0;                                  // ready for next replay
            __threadfence();
            atomicAdd(&g_gen, 1u);                         // release (single RMW)
        } else {
            while (ldcg_u32(&g_gen) == gen) { __nanosleep(32); }
        }
        __threadfence();                                   // acquire
    }
    __syncthreads();

    // ------------- phase 2: warp-per-bag gather-sum (exactly balanced) -----
    const int lane    = threadIdx.x & 31;
    const int nwarps  = gthreads >> 5;
    const int mywarp  = gtid >> 5;
    const int bpw     = (batch + nwarps - 1) / nwarps;   // == 2 at grid 1024
    const int bag_lo  = mywarp * bpw;
    const int bag_hi  = min(bag_lo + bpw, batch);

    const uint4* base = reinterpret_cast<const uint4*>(g_table_h) + lane;

    for (int bag = bag_lo; bag < bag_hi; ++bag) {
        const int start = __ldg(offs + bag);
        const int end   = (bag + 1 < batch) ? __ldg(offs + bag + 1) : n_total;

        float acc[8];
        {
            float4 b0 = __ldg(reinterpret_cast<const float4*>(bias) + 2 * lane);
            float4 b1 = __ldg(reinterpret_cast<const float4*>(bias) + 2 * lane + 1);
            acc[0] = b0.x; acc[1] = b0.y; acc[2] = b0.z; acc[3] = b0.w;
            acc[4] = b1.x; acc[5] = b1.y; acc[6] = b1.z; acc[7] = b1.w;
        }

        int j = start;
        for (; j + 4 <= end; j += 4) {
            const int i0 = __ldg(idx + j + 0);
            const int i1 = __ldg(idx + j + 1);
            const int i2 = __ldg(idx + j + 2);
            const int i3 = __ldg(idx + j + 3);
            const uint4 v0 = base[(size_t)i0 * ROW_U4];
            const uint4 v1 = base[(size_t)i1 * ROW_U4];
            const uint4 v2 = base[(size_t)i2 * ROW_U4];
            const uint4 v3 = base[(size_t)i3 * ROW_U4];
            tree4_acc(acc, v0, v1, v2, v3);
        }
        for (; j < end; ++j) {
            const int i = __ldg(idx + j);
            one_acc(acc, base[(size_t)i * ROW_U4]);
        }

        float4* o = reinterpret_cast<float4*>(out + (size_t)bag * HIDDEN) + 2 * lane;
        o[0] = make_float4(acc[0], acc[1], acc[2], acc[3]);
        o[1] = make_float4(acc[4], acc[5], acc[6], acc[7]);
    }
}

extern "C" void kernel_launch(void* const* d_in, const int* in_sizes, int n_in,
                              void* d_out, int out_size)
{
    const int*    feature_indices = (const int*)d_in[0];
    const int*    offsets         = (const int*)d_in[1];
    const float4* table4          = (const float4*)d_in[2];
    const float*  bias            = (const float*)d_in[3];
    float*        out             = (float*)d_out;

    const int n_total     = in_sizes[0];
    const int batch       = in_sizes[1];
    const int table_elems = in_sizes[2];
    const int n8          = table_elems / 8;

    // Grid: 1024 if co-residency allows (spin barrier requires all CTAs
    // resident in one wave). Host-only queries; deterministic.
    static int s_grid = 0;
    if (s_grid == 0) {
        int dev = 0, sms = 0, maxb = 0;
        cudaGetDevice(&dev);
        cudaDeviceGetAttribute(&sms, cudaDevAttrMultiProcessorCount, dev);
        cudaOccupancyMaxActiveBlocksPerMultiprocessor(&maxb, embag_fused3_kernel,
                                                      256, 0);
        if (sms <= 0)  sms = 148;
        if (maxb <= 0) maxb = 1;
        int cap = sms * maxb;
        s_grid = cap < 1024 ? cap : 1024;
    }

    embag_fused3_kernel<<<s_grid, 256>>>(feature_indices, offsets, table4, bias,
                                         out, batch, n_total, n8);
}

// round 14
// speedup vs baseline: 1.2756x; 1.1913x over previous
#include <cuda_runtime.h>
#include <cuda_fp16.h>
#include <cstdint>

// EmbeddingBag(mode='sum') + bias — final locked-in version.
//
// Closed performance model (validated over 12 rounds): runtime == total LTS
// (L2) bytes / chip LTS cap (~14.2 TB/s measured). The gather moves the
// irreducible 271MB (252MB fp16 rows + idx + out) -> 19.1us floor, reached
// by this body in four independent reproductions. Sub-fp16 table storage
// fails the 1e-3 error gate; SMEM/L1 restructurings and persistent fusion
// all lost to crossbar conflicts / zero per-SM reuse / barrier ramp skew.
//
// Structure:
//  1) convert fp32 table -> fp16 scratch (512-thread CTAs)
//  2) gather-sum, one warp per bag: LDG.128 rows, fp16 tree-of-4 partial
//     sums (rel_err 3.7e-4), fp32 accumulate + bias; launched with PDL so
//     its ramp + table-independent prologue overlap the convert.

#define HIDDEN   256
#define MAX_ROWS 6144
#define ROW_U4   32   // 256 halves = 512B = 32 uint4 per row

__device__ __half g_table_h[MAX_ROWS * HIDDEN];   // 3 MB scratch

__device__ __forceinline__ unsigned h2_to_u(__half2 h) {
    unsigned u; memcpy(&u, &h, 4); return u;
}
__device__ __forceinline__ __half2 u_to_h2(unsigned u) {
    __half2 h; memcpy(&h, &u, 4); return h;
}

// ---------------- phase 1: fp32 -> fp16 convert ----------------
__global__ __launch_bounds__(512)
void convert_kernel(const float4* __restrict__ table4, int n8)
{
    int t = blockIdx.x * blockDim.x + threadIdx.x;
    if (t < n8) {
        float4 a = __ldg(table4 + 2 * t);
        float4 b = __ldg(table4 + 2 * t + 1);
        uint4 v;
        v.x = h2_to_u(__floats2half2_rn(a.x, a.y));
        v.y = h2_to_u(__floats2half2_rn(a.z, a.w));
        v.z = h2_to_u(__floats2half2_rn(b.x, b.y));
        v.w = h2_to_u(__floats2half2_rn(b.z, b.w));
        reinterpret_cast<uint4*>(g_table_h)[t] = v;
    }
#if __CUDA_ARCH__ >= 900
    cudaTriggerProgrammaticLaunchCompletion();
#endif
}

// ---------------- phase 2: gather-sum ----------------
__device__ __forceinline__ void tree4_acc(float acc[8],
                                          const uint4& v0, const uint4& v1,
                                          const uint4& v2, const uint4& v3)
{
    __half2 s0 = __hadd2(__hadd2(u_to_h2(v0.x), u_to_h2(v1.x)),
                         __hadd2(u_to_h2(v2.x), u_to_h2(v3.x)));
    __half2 s1 = __hadd2(__hadd2(u_to_h2(v0.y), u_to_h2(v1.y)),
                         __hadd2(u_to_h2(v2.y), u_to_h2(v3.y)));
    __half2 s2 = __hadd2(__hadd2(u_to_h2(v0.z), u_to_h2(v1.z)),
                         __hadd2(u_to_h2(v2.z), u_to_h2(v3.z)));
    __half2 s3 = __hadd2(__hadd2(u_to_h2(v0.w), u_to_h2(v1.w)),
                         __hadd2(u_to_h2(v2.w), u_to_h2(v3.w)));
    float2 f0 = __half22float2(s0);
    float2 f1 = __half22float2(s1);
    float2 f2 = __half22float2(s2);
    float2 f3 = __half22float2(s3);
    acc[0] += f0.x; acc[1] += f0.y;
    acc[2] += f1.x; acc[3] += f1.y;
    acc[4] += f2.x; acc[5] += f2.y;
    acc[6] += f3.x; acc[7] += f3.y;
}

__device__ __forceinline__ void one_acc(float acc[8], const uint4& v)
{
    float2 f0 = __half22float2(u_to_h2(v.x));
    float2 f1 = __half22float2(u_to_h2(v.y));
    float2 f2 = __half22float2(u_to_h2(v.z));
    float2 f3 = __half22float2(u_to_h2(v.w));
    acc[0] += f0.x; acc[1] += f0.y;
    acc[2] += f1.x; acc[3] += f1.y;
    acc[4] += f2.x; acc[5] += f2.y;
    acc[6] += f3.x; acc[7] += f3.y;
}

__global__ __launch_bounds__(256)
void embag_h_kernel(const int* __restrict__ idx,
                    const int* __restrict__ offs,
                    const float* __restrict__ bias,
                    float* __restrict__ out,
                    int batch, int n_total)
{
    const int warp = (blockIdx.x * blockDim.x + threadIdx.x) >> 5;
    const int lane = threadIdx.x & 31;
    if (warp >= batch) {
#if __CUDA_ARCH__ >= 900
        cudaGridDependencySynchronize();
#endif
        return;
    }

    // ---- table-independent prologue (overlaps convert via PDL) ----
    const int start = __ldg(offs + warp);
    const int end   = (warp + 1 < batch) ? __ldg(offs + warp + 1) : n_total;

    float acc[8];
    {
        float4 b0 = __ldg(reinterpret_cast<const float4*>(bias) + 2 * lane);
        float4 b1 = __ldg(reinterpret_cast<const float4*>(bias) + 2 * lane + 1);
        acc[0] = b0.x; acc[1] = b0.y; acc[2] = b0.z; acc[3] = b0.w;
        acc[4] = b1.x; acc[5] = b1.y; acc[6] = b1.z; acc[7] = b1.w;
    }

    int j = start;
    int i0 = 0, i1 = 0, i2 = 0, i3 = 0;
    const bool has4 = (j + 4 <= end);
    if (has4) {
        i0 = __ldg(idx + j + 0);
        i1 = __ldg(idx + j + 1);
        i2 = __ldg(idx + j + 2);
        i3 = __ldg(idx + j + 3);
    }

#if __CUDA_ARCH__ >= 900
    cudaGridDependencySynchronize();   // convert complete past here
#endif

    const uint4* base = reinterpret_cast<const uint4*>(g_table_h) + lane;

    if (has4) {
        for (; j + 8 <= end; j += 4) {
            const int m0 = __ldg(idx + j + 4);
            const int m1 = __ldg(idx + j + 5);
            const int m2 = __ldg(idx + j + 6);
            const int m3 = __ldg(idx + j + 7);
            const uint4 v0 = base[(size_t)i0 * ROW_U4];
            const uint4 v1 = base[(size_t)i1 * ROW_U4];
            const uint4 v2 = base[(size_t)i2 * ROW_U4];
            const uint4 v3 = base[(size_t)i3 * ROW_U4];
            tree4_acc(acc, v0, v1, v2, v3);
            i0 = m0; i1 = m1; i2 = m2; i3 = m3;
        }
        const uint4 v0 = base[(size_t)i0 * ROW_U4];
        const uint4 v1 = base[(size_t)i1 * ROW_U4];
        const uint4 v2 = base[(size_t)i2 * ROW_U4];
        const uint4 v3 = base[(size_t)i3 * ROW_U4];
        tree4_acc(acc, v0, v1, v2, v3);
        j += 4;
    }
    for (; j < end; ++j) {
        const int i = __ldg(idx + j);
        one_acc(acc, base[(size_t)i * ROW_U4]);
    }

    float4* o = reinterpret_cast<float4*>(out + (size_t)warp * HIDDEN) + 2 * lane;
    o[0] = make_float4(acc[0], acc[1], acc[2], acc[3]);
    o[1] = make_float4(acc[4], acc[5], acc[6], acc[7]);
}

extern "C" void kernel_launch(void* const* d_in, const int* in_sizes, int n_in,
                              void* d_out, int out_size)
{
    const int*    feature_indices = (const int*)d_in[0];
    const int*    offsets         = (const int*)d_in[1];
    const float4* table4          = (const float4*)d_in[2];
    const float*  bias            = (const float*)d_in[3];
    float*        out             = (float*)d_out;

    const int n_total     = in_sizes[0];
    const int batch       = in_sizes[1];
    const int table_elems = in_sizes[2];
    const int n8          = table_elems / 8;

    convert_kernel<<<(n8 + 511) / 512, 512>>>(table4, n8);

    const int warps_per_block = 256 / 32;
    const int grid = (batch + warps_per_block - 1) / warps_per_block;

    cudaLaunchConfig_t cfg = {};
    cfg.gridDim  = dim3(grid, 1, 1);
    cfg.blockDim = dim3(256, 1, 1);
    cfg.dynamicSmemBytes = 0;
    cfg.stream = 0;
    cudaLaunchAttribute attrs[1];
    attrs[0].id = cudaLaunchAttributeProgrammaticStreamSerialization;
    attrs[0].val.programmaticStreamSerializationAllowed = 1;
    cfg.attrs = attrs;
    cfg.numAttrs = 1;

    cudaLaunchKernelEx(&cfg, embag_h_kernel,
                       feature_indices, offsets, bias, out, batch, n_total);
}

// round 15
// speedup vs baseline: 1.2912x; 1.0122x over previous
#include <cuda_runtime.h>
#include <cuda_fp16.h>
#include <cstdint>

// EmbeddingBag(mode='sum') + bias — final version (best-config re-bench).
//
// Closed model, validated over 13 rounds: runtime == total LTS (L2) bytes /
// chip LTS cap (~6300 B/cyc ~= 14.2 TB/s @NAT). The gather moves the
// irreducible 271MB (252MB fp16 rows + idx + out) -> 19.1us floor (ncu: no
// pipe >56%, L2% == practical-cap/theoretical-peak). Sub-fp16 storage fails
// the 1e-3 gate (8-bit: 3.9e-3) or trades bytes for a higher issue floor
// (12-bit decode ~50 inst/row -> ~20us). Fusion, SMEM slicing, L1 pass
// partitioning, deeper MLP: all empirically disproven. Remaining headroom
// is the prologue; 512-thread convert + PDL measured best (1.47us).
//
// Structure:
//  1) convert fp32 table -> fp16 scratch (512-thread CTAs, PDL trigger)
//  2) gather-sum, one warp per bag: LDG.128 rows, fp16 tree-of-4 partial
//     sums, fp32 accumulate + bias (rel_err 3.70e-4); PDL launch overlaps
//     its ramp + table-independent prologue with the convert.

#define HIDDEN   256
#define MAX_ROWS 6144
#define ROW_U4   32   // 256 halves = 512B = 32 uint4 per row

__device__ __half g_table_h[MAX_ROWS * HIDDEN];   // 3 MB scratch

__device__ __forceinline__ unsigned h2_to_u(__half2 h) {
    unsigned u; memcpy(&u, &h, 4); return u;
}
__device__ __forceinline__ __half2 u_to_h2(unsigned u) {
    __half2 h; memcpy(&h, &u, 4); return h;
}

// ---------------- phase 1: fp32 -> fp16 convert ----------------
__global__ __launch_bounds__(512)
void convert_kernel(const float4* __restrict__ table4, int n8)
{
    int t = blockIdx.x * blockDim.x + threadIdx.x;
    if (t < n8) {
        float4 a = __ldg(table4 + 2 * t);
        float4 b = __ldg(table4 + 2 * t + 1);
        uint4 v;
        v.x = h2_to_u(__floats2half2_rn(a.x, a.y));
        v.y = h2_to_u(__floats2half2_rn(a.z, a.w));
        v.z = h2_to_u(__floats2half2_rn(b.x, b.y));
        v.w = h2_to_u(__floats2half2_rn(b.z, b.w));
        reinterpret_cast<uint4*>(g_table_h)[t] = v;
    }
#if __CUDA_ARCH__ >= 900
    cudaTriggerProgrammaticLaunchCompletion();
#endif
}

// ---------------- phase 2: gather-sum ----------------
__device__ __forceinline__ void tree4_acc(float acc[8],
                                          const uint4& v0, const uint4& v1,
                                          const uint4& v2, const uint4& v3)
{
    __half2 s0 = __hadd2(__hadd2(u_to_h2(v0.x), u_to_h2(v1.x)),
                         __hadd2(u_to_h2(v2.x), u_to_h2(v3.x)));
    __half2 s1 = __hadd2(__hadd2(u_to_h2(v0.y), u_to_h2(v1.y)),
                         __hadd2(u_to_h2(v2.y), u_to_h2(v3.y)));
    __half2 s2 = __hadd2(__hadd2(u_to_h2(v0.z), u_to_h2(v1.z)),
                         __hadd2(u_to_h2(v2.z), u_to_h2(v3.z)));
    __half2 s3 = __hadd2(__hadd2(u_to_h2(v0.w), u_to_h2(v1.w)),
                         __hadd2(u_to_h2(v2.w), u_to_h2(v3.w)));
    float2 f0 = __half22float2(s0);
    float2 f1 = __half22float2(s1);
    float2 f2 = __half22float2(s2);
    float2 f3 = __half22float2(s3);
    acc[0] += f0.x; acc[1] += f0.y;
    acc[2] += f1.x; acc[3] += f1.y;
    acc[4] += f2.x; acc[5] += f2.y;
    acc[6] += f3.x; acc[7] += f3.y;
}

__device__ __forceinline__ void one_acc(float acc[8], const uint4& v)
{
    float2 f0 = __half22float2(u_to_h2(v.x));
    float2 f1 = __half22float2(u_to_h2(v.y));
    float2 f2 = __half22float2(u_to_h2(v.z));
    float2 f3 = __half22float2(u_to_h2(v.w));
    acc[0] += f0.x; acc[1] += f0.y;
    acc[2] += f1.x; acc[3] += f1.y;
    acc[4] += f2.x; acc[5] += f2.y;
    acc[6] += f3.x; acc[7] += f3.y;
}

__global__ __launch_bounds__(256)
void embag_h_kernel(const int* __restrict__ idx,
                    const int* __restrict__ offs,
                    const float* __restrict__ bias,
                    float* __restrict__ out,
                    int batch, int n_total)
{
    const int warp = (blockIdx.x * blockDim.x + threadIdx.x) >> 5;
    const int lane = threadIdx.x & 31;
    if (warp >= batch) {
#if __CUDA_ARCH__ >= 900
        cudaGridDependencySynchronize();
#endif
        return;
    }

    // ---- table-independent prologue (overlaps convert via PDL) ----
    const int start = __ldg(offs + warp);
    const int end   = (warp + 1 < batch) ? __ldg(offs + warp + 1) : n_total;

    float acc[8];
    {
        float4 b0 = __ldg(reinterpret_cast<const float4*>(bias) + 2 * lane);
        float4 b1 = __ldg(reinterpret_cast<const float4*>(bias) + 2 * lane + 1);
        acc[0] = b0.x; acc[1] = b0.y; acc[2] = b0.z; acc[3] = b0.w;
        acc[4] = b1.x; acc[5] = b1.y; acc[6] = b1.z; acc[7] = b1.w;
    }

    int j = start;
    int i0 = 0, i1 = 0, i2 = 0, i3 = 0;
    const bool has4 = (j + 4 <= end);
    if (has4) {
        i0 = __ldg(idx + j + 0);
        i1 = __ldg(idx + j + 1);
        i2 = __ldg(idx + j + 2);
        i3 = __ldg(idx + j + 3);
    }

#if __CUDA_ARCH__ >= 900
    cudaGridDependencySynchronize();   // convert complete past here
#endif

    const uint4* base = reinterpret_cast<const uint4*>(g_table_h) + lane;

    if (has4) {
        for (; j + 8 <= end; j += 4) {
            const int m0 = __ldg(idx + j + 4);
            const int m1 = __ldg(idx + j + 5);
            const int m2 = __ldg(idx + j + 6);
            const int m3 = __ldg(idx + j + 7);
            const uint4 v0 = base[(size_t)i0 * ROW_U4];
            const uint4 v1 = base[(size_t)i1 * ROW_U4];
            const uint4 v2 = base[(size_t)i2 * ROW_U4];
            const uint4 v3 = base[(size_t)i3 * ROW_U4];
            tree4_acc(acc, v0, v1, v2, v3);
            i0 = m0; i1 = m1; i2 = m2; i3 = m3;
        }
        const uint4 v0 = base[(size_t)i0 * ROW_U4];
        const uint4 v1 = base[(size_t)i1 * ROW_U4];
        const uint4 v2 = base[(size_t)i2 * ROW_U4];
        const uint4 v3 = base[(size_t)i3 * ROW_U4];
        tree4_acc(acc, v0, v1, v2, v3);
        j += 4;
    }
    for (; j < end; ++j) {
        const int i = __ldg(idx + j);
        one_acc(acc, base[(size_t)i * ROW_U4]);
    }

    float4* o = reinterpret_cast<float4*>(out + (size_t)warp * HIDDEN) + 2 * lane;
    o[0] = make_float4(acc[0], acc[1], acc[2], acc[3]);
    o[1] = make_float4(acc[4], acc[5], acc[6], acc[7]);
}

extern "C" void kernel_launch(void* const* d_in, const int* in_sizes, int n_in,
                              void* d_out, int out_size)
{
    const int*    feature_indices = (const int*)d_in[0];
    const int*    offsets         = (const int*)d_in[1];
    const float4* table4          = (const float4*)d_in[2];
    const float*  bias            = (const float*)d_in[3];
    float*        out             = (float*)d_out;

    const int n_total     = in_sizes[0];
    const int batch       = in_sizes[1];
    const int table_elems = in_sizes[2];
    const int n8          = table_elems / 8;

    convert_kernel<<<(n8 + 511) / 512, 512>>>(table4, n8);

    const int warps_per_block = 256 / 32;
    const int grid = (batch + warps_per_block - 1) / warps_per_block;

    cudaLaunchConfig_t cfg = {};
    cfg.gridDim  = dim3(grid, 1, 1);
    cfg.blockDim = dim3(256, 1, 1);
    cfg.dynamicSmemBytes = 0;
    cfg.stream = 0;
    cudaLaunchAttribute attrs[1];
    attrs[0].id = cudaLaunchAttributeProgrammaticStreamSerialization;
    attrs[0].val.programmaticStreamSerializationAllowed = 1;
    cfg.attrs = attrs;
    cfg.numAttrs = 1;

    cudaLaunchKernelEx(&cfg, embag_h_kernel,
                       feature_indices, offsets, bias, out, batch, n_total);
}